// round 2
// baseline (speedup 1.0000x reference)
#include <cuda_runtime.h>
#include <math.h>

#define BB 4
#define NN 40960
#define KK 16
#define HH 16
#define DD 32
#define BN_EPS 1e-5f

// scratch (device globals: no allocation allowed)
__device__ float g_feat_t[BB * NN * HH];   // feature transposed to [b, n, 16]
__device__ float g_agg1[BB * NN * HH];     // f_agg1 [b, n, 16]

__device__ __forceinline__ float lrelu(float y) { return fmaxf(y, 0.2f * y); }

// ---------------------------------------------------------------------------
// Transpose feature [B,16,N,1] -> [B*N,16]
// ---------------------------------------------------------------------------
__global__ void transpose_feat_kernel(const float* __restrict__ feature) {
    __shared__ float tile[HH][64 + 1];
    int b = blockIdx.y;
    int n0 = blockIdx.x * 64;
    int t = threadIdx.x;  // 256 threads
    int i = t & 63, cq = t >> 6;
    #pragma unroll
    for (int cc = cq; cc < HH; cc += 4)
        tile[cc][i] = feature[(b * HH + cc) * NN + n0 + i];
    __syncthreads();
    int c = t & 15, iq = t >> 4;
    #pragma unroll
    for (int ii = iq; ii < 64; ii += 16)
        g_feat_t[(b * NN + n0 + ii) * HH + c] = tile[c][ii];
}

// ---------------------------------------------------------------------------
// Stage 1: geometry + conv1(+BN,LReLU) + gather(feat) + att_pool_1 -> g_agg1
// One warp owns 8 CONSECUTIVE points. All indices + center xyz hoisted out of
// the loop (coalesced); neighbor gathers software-pipelined one iter ahead.
// ---------------------------------------------------------------------------
__global__ void __launch_bounds__(128) stage1_kernel(
    const float* __restrict__ xyz, const int* __restrict__ nidx,
    const float* __restrict__ w1, const float* __restrict__ b1,
    const float* __restrict__ g1, const float* __restrict__ be1,
    const float* __restrict__ fc1w, const float* __restrict__ fc1b,
    const float* __restrict__ ap1w, const float* __restrict__ ap1b,
    const float* __restrict__ ap1g, const float* __restrict__ ap1be)
{
    __shared__ __align__(16) float sh_fxyz[4][KK][12];
    __shared__ __align__(16) float sh_xcat[4][KK][DD];
    __shared__ __align__(16) float sh_agg[4][DD];
    __shared__ __align__(16) int   sh_idx[4][8][KK];
    __shared__ float sh_cxyz[4][8][3];

    const int warp = threadIdx.x >> 5;
    const int lane = threadIdx.x & 31;
    const int cm16 = lane & 15;
    const float inv_bn = rsqrtf(1.0f + BN_EPS);

    float w1r[10], b1f;
    {
        float s = g1[cm16] * inv_bn;
        #pragma unroll
        for (int i = 0; i < 10; i++) w1r[i] = w1[cm16 * 10 + i] * s;
        b1f = b1[cm16] * s + be1[cm16];
    }
    float fcr[DD], fcb;
    #pragma unroll
    for (int i = 0; i < DD; i++) fcr[i] = fc1w[lane * DD + i];
    fcb = fc1b[lane];
    float apr[DD], apb;
    {
        float s = ap1g[cm16] * inv_bn;
        #pragma unroll
        for (int i = 0; i < DD; i++) apr[i] = ap1w[cm16 * DD + i] * s;
        apb = ap1b[cm16] * s + ap1be[cm16];
    }

    const int b  = blockIdx.x / (NN / 32);
    const int n0 = (blockIdx.x % (NN / 32)) * 32;
    const int pbase = b * NN + n0 + warp * 8;   // first point of this warp

    // ---- hoisted coalesced loads: all 128 indices + 24 center coords ----
    {
        int4 iv = *(const int4*)(nidx + (size_t)pbase * KK + lane * 4);
        *(int4*)&sh_idx[warp][lane >> 2][(lane & 3) * 4] = iv;
    }
    if (lane < 24) {
        float v = xyz[pbase * 3 + lane];
        sh_cxyz[warp][lane / 3][lane % 3] = v;
    }
    __syncwarp();

    // ---- prefetch iteration 0 ----
    float p_x, p_y, p_z;
    float4 p_f0, p_f1;
    {
        int j = lane & 15;
        int idxn = sh_idx[warp][0][j];
        const float4* fb = (const float4*)(g_feat_t + (size_t)(b * NN + idxn) * HH);
        if (lane < 16) {
            const float* xb = xyz + (size_t)(b * NN + idxn) * 3;
            p_x = xb[0]; p_y = xb[1]; p_z = xb[2];
            p_f0 = fb[0]; p_f1 = fb[1];
        } else {
            p_f0 = fb[2]; p_f1 = fb[3];
        }
    }

    for (int t = 0; t < 8; t++) {
        const int pn = pbase + t;

        // -------- consume prefetched data --------
        if (lane < 16) {
            int j = lane;
            float cx = sh_cxyz[warp][t][0], cy = sh_cxyz[warp][t][1], cz = sh_cxyz[warp][t][2];
            float rx = cx - p_x, ry = cy - p_y, rz = cz - p_z;
            float dis = sqrtf(rx * rx + ry * ry + rz * rz);
            float4* row = (float4*)&sh_fxyz[warp][j][0];
            row[0] = make_float4(dis, rx, ry, rz);
            row[1] = make_float4(cx, cy, cz, p_x);
            ((float2*)&sh_fxyz[warp][j][8])[0] = make_float2(p_y, p_z);
            float4* dst = (float4*)&sh_xcat[warp][j][0];
            dst[0] = p_f0; dst[1] = p_f1;
        } else {
            int j = lane - 16;
            float4* dst = (float4*)&sh_xcat[warp][j][8];
            dst[0] = p_f0; dst[1] = p_f1;
        }

        // -------- prefetch next iteration --------
        if (t < 7) {
            int j = lane & 15;
            int idxn = sh_idx[warp][t + 1][j];
            const float4* fb = (const float4*)(g_feat_t + (size_t)(b * NN + idxn) * HH);
            if (lane < 16) {
                const float* xb = xyz + (size_t)(b * NN + idxn) * 3;
                p_x = xb[0]; p_y = xb[1]; p_z = xb[2];
                p_f0 = fb[0]; p_f1 = fb[1];
            } else {
                p_f0 = fb[2]; p_f1 = fb[3];
            }
        }
        __syncwarp();

        // -------- conv1 (10->16) + BN + LReLU --------
        {
            int jb = (lane >> 4) * 8;
            #pragma unroll
            for (int jj = 0; jj < 8; jj++) {
                int j = jb + jj;
                const float4* xr = (const float4*)&sh_fxyz[warp][j][0];
                float4 a = xr[0], bq = xr[1];
                float2 cq = ((const float2*)&sh_fxyz[warp][j][8])[0];
                float acc = b1f;
                acc += a.x * w1r[0] + a.y * w1r[1] + a.z * w1r[2] + a.w * w1r[3];
                acc += bq.x * w1r[4] + bq.y * w1r[5] + bq.z * w1r[6] + bq.w * w1r[7];
                acc += cq.x * w1r[8] + cq.y * w1r[9];
                sh_xcat[warp][j][HH + cm16] = lrelu(acc);
            }
        }
        __syncwarp();

        // -------- fc1 scores + softmax over k + weighted sum --------
        float sc[KK];
        #pragma unroll
        for (int j = 0; j < KK; j++) {
            const float4* xr = (const float4*)&sh_xcat[warp][j][0];
            float a0 = fcb, a1 = 0.0f;
            #pragma unroll
            for (int q = 0; q < 4; q++) {
                float4 v = xr[q];
                a0 += v.x * fcr[4 * q + 0] + v.y * fcr[4 * q + 1]
                    + v.z * fcr[4 * q + 2] + v.w * fcr[4 * q + 3];
            }
            #pragma unroll
            for (int q = 4; q < 8; q++) {
                float4 v = xr[q];
                a1 += v.x * fcr[4 * q + 0] + v.y * fcr[4 * q + 1]
                    + v.z * fcr[4 * q + 2] + v.w * fcr[4 * q + 3];
            }
            sc[j] = a0 + a1;
        }
        float ssum = 0.0f;
        #pragma unroll
        for (int j = 0; j < KK; j++) { sc[j] = __expf(sc[j]); ssum += sc[j]; }
        float inv = 1.0f / ssum;
        float agg = 0.0f;
        #pragma unroll
        for (int j = 0; j < KK; j++)
            agg += sh_xcat[warp][j][lane] * (sc[j] * inv);
        sh_agg[warp][lane] = agg;
        __syncwarp();

        // -------- mlp (32->16) + BN + LReLU, write f_agg1 --------
        if (lane < HH) {
            const float4* ag = (const float4*)&sh_agg[warp][0];
            float y0 = apb, y1 = 0.0f;
            #pragma unroll
            for (int q = 0; q < 4; q++) {
                float4 v = ag[q];
                y0 += v.x * apr[4 * q + 0] + v.y * apr[4 * q + 1]
                    + v.z * apr[4 * q + 2] + v.w * apr[4 * q + 3];
            }
            #pragma unroll
            for (int q = 4; q < 8; q++) {
                float4 v = ag[q];
                y1 += v.x * apr[4 * q + 0] + v.y * apr[4 * q + 1]
                    + v.z * apr[4 * q + 2] + v.w * apr[4 * q + 3];
            }
            g_agg1[(size_t)pn * HH + lane] = lrelu(y0 + y1);
        }
        __syncwarp();
    }
}

// ---------------------------------------------------------------------------
// Stage 2: recompute f_xyz1, conv2, gather(f_agg1), att_pool_2 -> output
// Same pipelined structure. Output staged in shared for coalesced stores.
// ---------------------------------------------------------------------------
__global__ void __launch_bounds__(128) stage2_kernel(
    const float* __restrict__ xyz, const int* __restrict__ nidx,
    const float* __restrict__ w1, const float* __restrict__ b1,
    const float* __restrict__ g1, const float* __restrict__ be1,
    const float* __restrict__ w2, const float* __restrict__ b2,
    const float* __restrict__ g2, const float* __restrict__ be2,
    const float* __restrict__ fc2w, const float* __restrict__ fc2b,
    const float* __restrict__ ap2w, const float* __restrict__ ap2b,
    const float* __restrict__ ap2g, const float* __restrict__ ap2be,
    float* __restrict__ out)
{
    __shared__ __align__(16) float sh_fxyz[4][KK][12];
    __shared__ __align__(16) float sh_fx1[4][KK][HH];
    __shared__ __align__(16) float sh_xcat[4][KK][DD];
    __shared__ __align__(16) float sh_agg[4][DD];
    __shared__ __align__(16) int   sh_idx[4][8][KK];
    __shared__ float sh_cxyz[4][8][3];
    __shared__ float sh_out[DD][33];

    const int warp = threadIdx.x >> 5;
    const int lane = threadIdx.x & 31;
    const int cm16 = lane & 15;
    const float inv_bn = rsqrtf(1.0f + BN_EPS);

    float w1r[10], b1f;
    {
        float s = g1[cm16] * inv_bn;
        #pragma unroll
        for (int i = 0; i < 10; i++) w1r[i] = w1[cm16 * 10 + i] * s;
        b1f = b1[cm16] * s + be1[cm16];
    }
    float w2r[HH], b2f;
    {
        float s = g2[cm16] * inv_bn;
        #pragma unroll
        for (int i = 0; i < HH; i++) w2r[i] = w2[cm16 * HH + i] * s;
        b2f = b2[cm16] * s + be2[cm16];
    }
    float fcr[DD], fcb;
    #pragma unroll
    for (int i = 0; i < DD; i++) fcr[i] = fc2w[lane * DD + i];
    fcb = fc2b[lane];
    float apr[DD], apb;
    {
        float s = ap2g[lane] * inv_bn;
        #pragma unroll
        for (int i = 0; i < DD; i++) apr[i] = ap2w[lane * DD + i] * s;
        apb = ap2b[lane] * s + ap2be[lane];
    }

    const int b  = blockIdx.x / (NN / 32);
    const int n0 = (blockIdx.x % (NN / 32)) * 32;
    const int pbase = b * NN + n0 + warp * 8;

    {
        int4 iv = *(const int4*)(nidx + (size_t)pbase * KK + lane * 4);
        *(int4*)&sh_idx[warp][lane >> 2][(lane & 3) * 4] = iv;
    }
    if (lane < 24) {
        float v = xyz[pbase * 3 + lane];
        sh_cxyz[warp][lane / 3][lane % 3] = v;
    }
    __syncwarp();

    float p_x, p_y, p_z;
    float4 p_f0, p_f1;
    {
        int j = lane & 15;
        int idxn = sh_idx[warp][0][j];
        const float4* fb = (const float4*)(g_agg1 + (size_t)(b * NN + idxn) * HH);
        if (lane < 16) {
            const float* xb = xyz + (size_t)(b * NN + idxn) * 3;
            p_x = xb[0]; p_y = xb[1]; p_z = xb[2];
            p_f0 = fb[0]; p_f1 = fb[1];
        } else {
            p_f0 = fb[2]; p_f1 = fb[3];
        }
    }

    for (int t = 0; t < 8; t++) {
        const int ln = warp * 8 + t;   // local point in [0,32)

        // -------- consume prefetched data --------
        if (lane < 16) {
            int j = lane;
            float cx = sh_cxyz[warp][t][0], cy = sh_cxyz[warp][t][1], cz = sh_cxyz[warp][t][2];
            float rx = cx - p_x, ry = cy - p_y, rz = cz - p_z;
            float dis = sqrtf(rx * rx + ry * ry + rz * rz);
            float4* row = (float4*)&sh_fxyz[warp][j][0];
            row[0] = make_float4(dis, rx, ry, rz);
            row[1] = make_float4(cx, cy, cz, p_x);
            ((float2*)&sh_fxyz[warp][j][8])[0] = make_float2(p_y, p_z);
            float4* dst = (float4*)&sh_xcat[warp][j][0];
            dst[0] = p_f0; dst[1] = p_f1;
        } else {
            int j = lane - 16;
            float4* dst = (float4*)&sh_xcat[warp][j][8];
            dst[0] = p_f0; dst[1] = p_f1;
        }

        // -------- prefetch next iteration --------
        if (t < 7) {
            int j = lane & 15;
            int idxn = sh_idx[warp][t + 1][j];
            const float4* fb = (const float4*)(g_agg1 + (size_t)(b * NN + idxn) * HH);
            if (lane < 16) {
                const float* xb = xyz + (size_t)(b * NN + idxn) * 3;
                p_x = xb[0]; p_y = xb[1]; p_z = xb[2];
                p_f0 = fb[0]; p_f1 = fb[1];
            } else {
                p_f0 = fb[2]; p_f1 = fb[3];
            }
        }
        __syncwarp();

        // -------- conv1 recompute (10->16) -> sh_fx1 --------
        {
            int jb = (lane >> 4) * 8;
            #pragma unroll
            for (int jj = 0; jj < 8; jj++) {
                int j = jb + jj;
                const float4* xr = (const float4*)&sh_fxyz[warp][j][0];
                float4 a = xr[0], bq = xr[1];
                float2 cq = ((const float2*)&sh_fxyz[warp][j][8])[0];
                float acc = b1f;
                acc += a.x * w1r[0] + a.y * w1r[1] + a.z * w1r[2] + a.w * w1r[3];
                acc += bq.x * w1r[4] + bq.y * w1r[5] + bq.z * w1r[6] + bq.w * w1r[7];
                acc += cq.x * w1r[8] + cq.y * w1r[9];
                sh_fx1[warp][j][cm16] = lrelu(acc);
            }
        }
        __syncwarp();

        // -------- conv2 (16->16) + BN + LReLU -> sh_xcat[:,16:] --------
        {
            int jb = (lane >> 4) * 8;
            #pragma unroll
            for (int jj = 0; jj < 8; jj++) {
                int j = jb + jj;
                const float4* xr = (const float4*)&sh_fx1[warp][j][0];
                float acc0 = b2f, acc1 = 0.0f;
                #pragma unroll
                for (int q = 0; q < 2; q++) {
                    float4 v = xr[q];
                    acc0 += v.x * w2r[4 * q + 0] + v.y * w2r[4 * q + 1]
                          + v.z * w2r[4 * q + 2] + v.w * w2r[4 * q + 3];
                }
                #pragma unroll
                for (int q = 2; q < 4; q++) {
                    float4 v = xr[q];
                    acc1 += v.x * w2r[4 * q + 0] + v.y * w2r[4 * q + 1]
                          + v.z * w2r[4 * q + 2] + v.w * w2r[4 * q + 3];
                }
                sh_xcat[warp][j][HH + cm16] = lrelu(acc0 + acc1);
            }
        }
        __syncwarp();

        // -------- fc2 + softmax + weighted sum --------
        float sc[KK];
        #pragma unroll
        for (int j = 0; j < KK; j++) {
            const float4* xr = (const float4*)&sh_xcat[warp][j][0];
            float a0 = fcb, a1 = 0.0f;
            #pragma unroll
            for (int q = 0; q < 4; q++) {
                float4 v = xr[q];
                a0 += v.x * fcr[4 * q + 0] + v.y * fcr[4 * q + 1]
                    + v.z * fcr[4 * q + 2] + v.w * fcr[4 * q + 3];
            }
            #pragma unroll
            for (int q = 4; q < 8; q++) {
                float4 v = xr[q];
                a1 += v.x * fcr[4 * q + 0] + v.y * fcr[4 * q + 1]
                    + v.z * fcr[4 * q + 2] + v.w * fcr[4 * q + 3];
            }
            sc[j] = a0 + a1;
        }
        float ssum = 0.0f;
        #pragma unroll
        for (int j = 0; j < KK; j++) { sc[j] = __expf(sc[j]); ssum += sc[j]; }
        float inv = 1.0f / ssum;
        float agg = 0.0f;
        #pragma unroll
        for (int j = 0; j < KK; j++)
            agg += sh_xcat[warp][j][lane] * (sc[j] * inv);
        sh_agg[warp][lane] = agg;
        __syncwarp();

        // -------- mlp2 (32->32) + BN + LReLU -> staged output --------
        {
            const float4* ag = (const float4*)&sh_agg[warp][0];
            float y0 = apb, y1 = 0.0f;
            #pragma unroll
            for (int q = 0; q < 4; q++) {
                float4 v = ag[q];
                y0 += v.x * apr[4 * q + 0] + v.y * apr[4 * q + 1]
                    + v.z * apr[4 * q + 2] + v.w * apr[4 * q + 3];
            }
            #pragma unroll
            for (int q = 4; q < 8; q++) {
                float4 v = ag[q];
                y1 += v.x * apr[4 * q + 0] + v.y * apr[4 * q + 1]
                    + v.z * apr[4 * q + 2] + v.w * apr[4 * q + 3];
            }
            sh_out[lane][ln] = lrelu(y0 + y1);
        }
        __syncwarp();
    }

    __syncthreads();
    for (int e = threadIdx.x; e < DD * 32; e += 128) {
        int c = e >> 5, ln = e & 31;
        out[((size_t)b * DD + c) * NN + n0 + ln] = sh_out[c][ln];
    }
}

// ---------------------------------------------------------------------------
extern "C" void kernel_launch(void* const* d_in, const int* in_sizes, int n_in,
                              void* d_out, int out_size) {
    const float* xyz     = (const float*)d_in[0];
    const float* feature = (const float*)d_in[1];
    const int*   nidx    = (const int*)  d_in[2];
    const float* w1   = (const float*)d_in[3];
    const float* b1   = (const float*)d_in[4];
    const float* g1   = (const float*)d_in[5];
    const float* be1  = (const float*)d_in[6];
    const float* fc1w = (const float*)d_in[7];
    const float* fc1b = (const float*)d_in[8];
    const float* ap1w = (const float*)d_in[9];
    const float* ap1b = (const float*)d_in[10];
    const float* ap1g = (const float*)d_in[11];
    const float* ap1be= (const float*)d_in[12];
    const float* w2   = (const float*)d_in[13];
    const float* b2   = (const float*)d_in[14];
    const float* g2   = (const float*)d_in[15];
    const float* be2  = (const float*)d_in[16];
    const float* fc2w = (const float*)d_in[17];
    const float* fc2b = (const float*)d_in[18];
    const float* ap2w = (const float*)d_in[19];
    const float* ap2b = (const float*)d_in[20];
    const float* ap2g = (const float*)d_in[21];
    const float* ap2be= (const float*)d_in[22];
    float* out = (float*)d_out;

    transpose_feat_kernel<<<dim3(NN / 64, BB), 256>>>(feature);
    stage1_kernel<<<BB * NN / 32, 128>>>(xyz, nidx, w1, b1, g1, be1,
                                         fc1w, fc1b, ap1w, ap1b, ap1g, ap1be);
    stage2_kernel<<<BB * NN / 32, 128>>>(xyz, nidx, w1, b1, g1, be1,
                                         w2, b2, g2, be2, fc2w, fc2b,
                                         ap2w, ap2b, ap2g, ap2be, out);
}

// round 3
// speedup vs baseline: 1.0925x; 1.0925x over previous
#include <cuda_runtime.h>
#include <math.h>

#define BB 4
#define NN 40960
#define KK 16
#define HH 16
#define DD 32
#define BN_EPS 1e-5f

typedef unsigned long long u64t;

// scratch (device globals: no allocation allowed)
__device__ float g_feat_t[BB * NN * HH];   // feature transposed to [b, n, 16]
__device__ float g_agg1[BB * NN * HH];     // f_agg1 [b, n, 16]

__device__ __forceinline__ float lrelu(float y) { return fmaxf(y, 0.2f * y); }

// ---- packed f32x2 helpers (sm_100+) ----
__device__ __forceinline__ void FMA2(u64t& d, u64t a, u64t b) {
    asm("fma.rn.f32x2 %0, %1, %2, %0;" : "+l"(d) : "l"(a), "l"(b));
}
__device__ __forceinline__ void ADD2(u64t& d, u64t a) {
    asm("add.rn.f32x2 %0, %0, %1;" : "+l"(d) : "l"(a));
}
__device__ __forceinline__ u64t PACK2(float lo, float hi) {
    u64t r; asm("mov.b64 %0, {%1, %2};" : "=l"(r) : "f"(lo), "f"(hi)); return r;
}
__device__ __forceinline__ float HSUM2(u64t v) {
    float lo, hi; asm("mov.b64 {%0, %1}, %2;" : "=f"(lo), "=f"(hi) : "l"(v));
    return lo + hi;
}
__device__ __forceinline__ void LDS2x64(u64t& a, u64t& b, unsigned addr) {
    asm volatile("ld.shared.v2.b64 {%0, %1}, [%2];" : "=l"(a), "=l"(b) : "r"(addr));
}
__device__ __forceinline__ u64t LDS64(unsigned addr) {
    u64t a; asm volatile("ld.shared.b64 %0, [%1];" : "=l"(a) : "r"(addr)); return a;
}

// ---------------------------------------------------------------------------
// Transpose feature [B,16,N,1] -> [B*N,16]
// ---------------------------------------------------------------------------
__global__ void transpose_feat_kernel(const float* __restrict__ feature) {
    __shared__ float tile[HH][64 + 1];
    int b = blockIdx.y;
    int n0 = blockIdx.x * 64;
    int t = threadIdx.x;  // 256 threads
    int i = t & 63, cq = t >> 6;
    #pragma unroll
    for (int cc = cq; cc < HH; cc += 4)
        tile[cc][i] = feature[(b * HH + cc) * NN + n0 + i];
    __syncthreads();
    int c = t & 15, iq = t >> 4;
    #pragma unroll
    for (int ii = iq; ii < 64; ii += 16)
        g_feat_t[(b * NN + n0 + ii) * HH + c] = tile[c][ii];
}

// ---------------------------------------------------------------------------
// Stage 1: geometry + conv1(+BN,LReLU) + gather(feat) + att_pool_1 -> g_agg1
// ---------------------------------------------------------------------------
__global__ void __launch_bounds__(128) stage1_kernel(
    const float* __restrict__ xyz, const int* __restrict__ nidx,
    const float* __restrict__ w1, const float* __restrict__ b1,
    const float* __restrict__ g1, const float* __restrict__ be1,
    const float* __restrict__ fc1w, const float* __restrict__ fc1b,
    const float* __restrict__ ap1w, const float* __restrict__ ap1b,
    const float* __restrict__ ap1g, const float* __restrict__ ap1be)
{
    __shared__ __align__(16) float sh_fxyz[4][KK][12];
    __shared__ __align__(16) float sh_xcat[4][KK][DD];
    __shared__ __align__(16) float sh_agg[4][DD];
    __shared__ __align__(16) int   sh_idx[4][8][KK];
    __shared__ float sh_cxyz[4][8][3];

    const int warp = threadIdx.x >> 5;
    const int lane = threadIdx.x & 31;
    const int cm16 = lane & 15;
    const float inv_bn = rsqrtf(1.0f + BN_EPS);

    // packed weights (BN folded)
    u64t w1p[5]; float b1f;
    {
        float s = g1[cm16] * inv_bn;
        #pragma unroll
        for (int i = 0; i < 5; i++)
            w1p[i] = PACK2(w1[cm16 * 10 + 2 * i] * s, w1[cm16 * 10 + 2 * i + 1] * s);
        b1f = b1[cm16] * s + be1[cm16];
    }
    u64t fcp[16]; float fcb = fc1b[lane];
    #pragma unroll
    for (int i = 0; i < 16; i++)
        fcp[i] = PACK2(fc1w[lane * DD + 2 * i], fc1w[lane * DD + 2 * i + 1]);
    u64t app[16]; float apb;
    {
        float s = ap1g[cm16] * inv_bn;
        #pragma unroll
        for (int i = 0; i < 16; i++)
            app[i] = PACK2(ap1w[cm16 * DD + 2 * i] * s, ap1w[cm16 * DD + 2 * i + 1] * s);
        apb = ap1b[cm16] * s + ap1be[cm16];
    }

    const int b  = blockIdx.x / (NN / 32);
    const int n0 = (blockIdx.x % (NN / 32)) * 32;
    const int pbase = b * NN + n0 + warp * 8;

    const unsigned fxyz_a = (unsigned)__cvta_generic_to_shared(&sh_fxyz[warp][0][0]);
    const unsigned xcat_a = (unsigned)__cvta_generic_to_shared(&sh_xcat[warp][0][0]);
    const unsigned agg_a  = (unsigned)__cvta_generic_to_shared(&sh_agg[warp][0]);

    // hoisted coalesced loads: all 128 indices + 24 center coords
    {
        int4 iv = *(const int4*)(nidx + (size_t)pbase * KK + lane * 4);
        *(int4*)&sh_idx[warp][lane >> 2][(lane & 3) * 4] = iv;
    }
    if (lane < 24) sh_cxyz[warp][lane / 3][lane % 3] = xyz[pbase * 3 + lane];
    __syncwarp();

    for (int t = 0; t < 8; t++) {
        const int pn = pbase + t;

        // -------- geometry (lane<16) --------
        if (lane < KK) {
            int j = lane;
            int idx = sh_idx[warp][t][j];
            float cx = sh_cxyz[warp][t][0], cy = sh_cxyz[warp][t][1], cz = sh_cxyz[warp][t][2];
            const float* np_ = xyz + (size_t)(b * NN + idx) * 3;
            float nx = np_[0], ny = np_[1], nz = np_[2];
            float rx = cx - nx, ry = cy - ny, rz = cz - nz;
            float dis = sqrtf(rx * rx + ry * ry + rz * rz);
            float4* row = (float4*)&sh_fxyz[warp][j][0];
            row[0] = make_float4(dis, rx, ry, rz);
            row[1] = make_float4(cx, cy, cz, nx);
            ((float2*)&sh_fxyz[warp][j][8])[0] = make_float2(ny, nz);
        }
        // -------- gather f_nb (all lanes) --------
        {
            int j = lane >> 1, h = lane & 1;
            int idx = sh_idx[warp][t][j];
            const float4* src = (const float4*)(g_feat_t + (size_t)(b * NN + idx) * HH + h * 8);
            float4 v0 = src[0], v1 = src[1];
            float4* dst = (float4*)&sh_xcat[warp][j][h * 8];
            dst[0] = v0; dst[1] = v1;
        }
        __syncwarp();

        // -------- conv1 (10->16) + BN + LReLU --------
        {
            int jb = (lane >> 4) * 8;
            #pragma unroll
            for (int jj = 0; jj < 8; jj++) {
                int j = jb + jj;
                unsigned a = fxyz_a + j * 48;
                u64t x0, x1, x2, x3, x4;
                LDS2x64(x0, x1, a);
                LDS2x64(x2, x3, a + 16);
                x4 = LDS64(a + 32);
                u64t acc0 = PACK2(b1f, 0.f), acc1 = PACK2(0.f, 0.f);
                FMA2(acc0, x0, w1p[0]); FMA2(acc1, x1, w1p[1]);
                FMA2(acc0, x2, w1p[2]); FMA2(acc1, x3, w1p[3]);
                FMA2(acc0, x4, w1p[4]);
                ADD2(acc0, acc1);
                sh_xcat[warp][j][HH + cm16] = lrelu(HSUM2(acc0));
            }
        }
        __syncwarp();

        // -------- fc1 scores + softmax over k + weighted sum --------
        float sc[KK];
        #pragma unroll
        for (int j = 0; j < KK; j++) {
            unsigned a = xcat_a + j * 128;
            u64t p0, p1, p2, p3;
            u64t acc0 = PACK2(fcb, 0.f), acc1 = PACK2(0.f, 0.f);
            LDS2x64(p0, p1, a);      FMA2(acc0, p0, fcp[0]);  FMA2(acc1, p1, fcp[1]);
            LDS2x64(p2, p3, a + 16); FMA2(acc0, p2, fcp[2]);  FMA2(acc1, p3, fcp[3]);
            LDS2x64(p0, p1, a + 32); FMA2(acc0, p0, fcp[4]);  FMA2(acc1, p1, fcp[5]);
            LDS2x64(p2, p3, a + 48); FMA2(acc0, p2, fcp[6]);  FMA2(acc1, p3, fcp[7]);
            LDS2x64(p0, p1, a + 64); FMA2(acc0, p0, fcp[8]);  FMA2(acc1, p1, fcp[9]);
            LDS2x64(p2, p3, a + 80); FMA2(acc0, p2, fcp[10]); FMA2(acc1, p3, fcp[11]);
            LDS2x64(p0, p1, a + 96); FMA2(acc0, p0, fcp[12]); FMA2(acc1, p1, fcp[13]);
            LDS2x64(p2, p3, a + 112);FMA2(acc0, p2, fcp[14]); FMA2(acc1, p3, fcp[15]);
            ADD2(acc0, acc1);
            sc[j] = HSUM2(acc0);
        }
        float ssum = 0.0f;
        #pragma unroll
        for (int j = 0; j < KK; j++) { sc[j] = __expf(sc[j]); ssum += sc[j]; }
        float inv = 1.0f / ssum;
        float agg = 0.0f;
        #pragma unroll
        for (int j = 0; j < KK; j++)
            agg += sh_xcat[warp][j][lane] * (sc[j] * inv);
        sh_agg[warp][lane] = agg;
        __syncwarp();

        // -------- mlp (32->16) + BN + LReLU, write f_agg1 --------
        if (lane < HH) {
            u64t acc0 = PACK2(apb, 0.f), acc1 = PACK2(0.f, 0.f);
            #pragma unroll
            for (int q = 0; q < 8; q++) {
                u64t p0, p1;
                LDS2x64(p0, p1, agg_a + q * 16);
                FMA2(acc0, p0, app[2 * q]);
                FMA2(acc1, p1, app[2 * q + 1]);
            }
            ADD2(acc0, acc1);
            g_agg1[(size_t)pn * HH + lane] = lrelu(HSUM2(acc0));
        }
        __syncwarp();
    }
}

// ---------------------------------------------------------------------------
// Stage 2: recompute f_xyz1, conv2, gather(f_agg1), att_pool_2 -> output
// ---------------------------------------------------------------------------
__global__ void __launch_bounds__(128) stage2_kernel(
    const float* __restrict__ xyz, const int* __restrict__ nidx,
    const float* __restrict__ w1, const float* __restrict__ b1,
    const float* __restrict__ g1, const float* __restrict__ be1,
    const float* __restrict__ w2, const float* __restrict__ b2,
    const float* __restrict__ g2, const float* __restrict__ be2,
    const float* __restrict__ fc2w, const float* __restrict__ fc2b,
    const float* __restrict__ ap2w, const float* __restrict__ ap2b,
    const float* __restrict__ ap2g, const float* __restrict__ ap2be,
    float* __restrict__ out)
{
    __shared__ __align__(16) float sh_fxyz[4][KK][12];
    __shared__ __align__(16) float sh_fx1[4][KK][HH];
    __shared__ __align__(16) float sh_xcat[4][KK][DD];
    __shared__ __align__(16) float sh_agg[4][DD];
    __shared__ __align__(16) int   sh_idx[4][8][KK];
    __shared__ float sh_cxyz[4][8][3];
    __shared__ float sh_out[DD][33];

    const int warp = threadIdx.x >> 5;
    const int lane = threadIdx.x & 31;
    const int cm16 = lane & 15;
    const float inv_bn = rsqrtf(1.0f + BN_EPS);

    u64t w1p[5]; float b1f;
    {
        float s = g1[cm16] * inv_bn;
        #pragma unroll
        for (int i = 0; i < 5; i++)
            w1p[i] = PACK2(w1[cm16 * 10 + 2 * i] * s, w1[cm16 * 10 + 2 * i + 1] * s);
        b1f = b1[cm16] * s + be1[cm16];
    }
    u64t w2p[8]; float b2f;
    {
        float s = g2[cm16] * inv_bn;
        #pragma unroll
        for (int i = 0; i < 8; i++)
            w2p[i] = PACK2(w2[cm16 * HH + 2 * i] * s, w2[cm16 * HH + 2 * i + 1] * s);
        b2f = b2[cm16] * s + be2[cm16];
    }
    u64t fcp[16]; float fcb = fc2b[lane];
    #pragma unroll
    for (int i = 0; i < 16; i++)
        fcp[i] = PACK2(fc2w[lane * DD + 2 * i], fc2w[lane * DD + 2 * i + 1]);
    u64t app[16]; float apb;
    {
        float s = ap2g[lane] * inv_bn;
        #pragma unroll
        for (int i = 0; i < 16; i++)
            app[i] = PACK2(ap2w[lane * DD + 2 * i] * s, ap2w[lane * DD + 2 * i + 1] * s);
        apb = ap2b[lane] * s + ap2be[lane];
    }

    const int b  = blockIdx.x / (NN / 32);
    const int n0 = (blockIdx.x % (NN / 32)) * 32;
    const int pbase = b * NN + n0 + warp * 8;

    const unsigned fxyz_a = (unsigned)__cvta_generic_to_shared(&sh_fxyz[warp][0][0]);
    const unsigned fx1_a  = (unsigned)__cvta_generic_to_shared(&sh_fx1[warp][0][0]);
    const unsigned xcat_a = (unsigned)__cvta_generic_to_shared(&sh_xcat[warp][0][0]);
    const unsigned agg_a  = (unsigned)__cvta_generic_to_shared(&sh_agg[warp][0]);

    {
        int4 iv = *(const int4*)(nidx + (size_t)pbase * KK + lane * 4);
        *(int4*)&sh_idx[warp][lane >> 2][(lane & 3) * 4] = iv;
    }
    if (lane < 24) sh_cxyz[warp][lane / 3][lane % 3] = xyz[pbase * 3 + lane];
    __syncwarp();

    for (int t = 0; t < 8; t++) {
        const int ln = warp * 8 + t;   // local point in [0,32)

        if (lane < KK) {
            int j = lane;
            int idx = sh_idx[warp][t][j];
            float cx = sh_cxyz[warp][t][0], cy = sh_cxyz[warp][t][1], cz = sh_cxyz[warp][t][2];
            const float* np_ = xyz + (size_t)(b * NN + idx) * 3;
            float nx = np_[0], ny = np_[1], nz = np_[2];
            float rx = cx - nx, ry = cy - ny, rz = cz - nz;
            float dis = sqrtf(rx * rx + ry * ry + rz * rz);
            float4* row = (float4*)&sh_fxyz[warp][j][0];
            row[0] = make_float4(dis, rx, ry, rz);
            row[1] = make_float4(cx, cy, cz, nx);
            ((float2*)&sh_fxyz[warp][j][8])[0] = make_float2(ny, nz);
        }
        // gather f_nb2 from g_agg1
        {
            int j = lane >> 1, h = lane & 1;
            int idx = sh_idx[warp][t][j];
            const float4* src = (const float4*)(g_agg1 + (size_t)(b * NN + idx) * HH + h * 8);
            float4 v0 = src[0], v1 = src[1];
            float4* dst = (float4*)&sh_xcat[warp][j][h * 8];
            dst[0] = v0; dst[1] = v1;
        }
        __syncwarp();

        // conv1 recompute (10->16) -> sh_fx1
        {
            int jb = (lane >> 4) * 8;
            #pragma unroll
            for (int jj = 0; jj < 8; jj++) {
                int j = jb + jj;
                unsigned a = fxyz_a + j * 48;
                u64t x0, x1, x2, x3, x4;
                LDS2x64(x0, x1, a);
                LDS2x64(x2, x3, a + 16);
                x4 = LDS64(a + 32);
                u64t acc0 = PACK2(b1f, 0.f), acc1 = PACK2(0.f, 0.f);
                FMA2(acc0, x0, w1p[0]); FMA2(acc1, x1, w1p[1]);
                FMA2(acc0, x2, w1p[2]); FMA2(acc1, x3, w1p[3]);
                FMA2(acc0, x4, w1p[4]);
                ADD2(acc0, acc1);
                sh_fx1[warp][j][cm16] = lrelu(HSUM2(acc0));
            }
        }
        __syncwarp();

        // conv2 (16->16) + BN + LReLU -> sh_xcat[:,16:]
        {
            int jb = (lane >> 4) * 8;
            #pragma unroll
            for (int jj = 0; jj < 8; jj++) {
                int j = jb + jj;
                unsigned a = fx1_a + j * 64;
                u64t p0, p1, p2, p3;
                u64t acc0 = PACK2(b2f, 0.f), acc1 = PACK2(0.f, 0.f);
                LDS2x64(p0, p1, a);      FMA2(acc0, p0, w2p[0]); FMA2(acc1, p1, w2p[1]);
                LDS2x64(p2, p3, a + 16); FMA2(acc0, p2, w2p[2]); FMA2(acc1, p3, w2p[3]);
                LDS2x64(p0, p1, a + 32); FMA2(acc0, p0, w2p[4]); FMA2(acc1, p1, w2p[5]);
                LDS2x64(p2, p3, a + 48); FMA2(acc0, p2, w2p[6]); FMA2(acc1, p3, w2p[7]);
                ADD2(acc0, acc1);
                sh_xcat[warp][j][HH + cm16] = lrelu(HSUM2(acc0));
            }
        }
        __syncwarp();

        // fc2 + softmax + weighted sum
        float sc[KK];
        #pragma unroll
        for (int j = 0; j < KK; j++) {
            unsigned a = xcat_a + j * 128;
            u64t p0, p1, p2, p3;
            u64t acc0 = PACK2(fcb, 0.f), acc1 = PACK2(0.f, 0.f);
            LDS2x64(p0, p1, a);      FMA2(acc0, p0, fcp[0]);  FMA2(acc1, p1, fcp[1]);
            LDS2x64(p2, p3, a + 16); FMA2(acc0, p2, fcp[2]);  FMA2(acc1, p3, fcp[3]);
            LDS2x64(p0, p1, a + 32); FMA2(acc0, p0, fcp[4]);  FMA2(acc1, p1, fcp[5]);
            LDS2x64(p2, p3, a + 48); FMA2(acc0, p2, fcp[6]);  FMA2(acc1, p3, fcp[7]);
            LDS2x64(p0, p1, a + 64); FMA2(acc0, p0, fcp[8]);  FMA2(acc1, p1, fcp[9]);
            LDS2x64(p2, p3, a + 80); FMA2(acc0, p2, fcp[10]); FMA2(acc1, p3, fcp[11]);
            LDS2x64(p0, p1, a + 96); FMA2(acc0, p0, fcp[12]); FMA2(acc1, p1, fcp[13]);
            LDS2x64(p2, p3, a + 112);FMA2(acc0, p2, fcp[14]); FMA2(acc1, p3, fcp[15]);
            ADD2(acc0, acc1);
            sc[j] = HSUM2(acc0);
        }
        float ssum = 0.0f;
        #pragma unroll
        for (int j = 0; j < KK; j++) { sc[j] = __expf(sc[j]); ssum += sc[j]; }
        float inv = 1.0f / ssum;
        float agg = 0.0f;
        #pragma unroll
        for (int j = 0; j < KK; j++)
            agg += sh_xcat[warp][j][lane] * (sc[j] * inv);
        sh_agg[warp][lane] = agg;
        __syncwarp();

        // mlp2 (32->32) + BN + LReLU -> staged output
        {
            u64t acc0 = PACK2(apb, 0.f), acc1 = PACK2(0.f, 0.f);
            #pragma unroll
            for (int q = 0; q < 8; q++) {
                u64t p0, p1;
                LDS2x64(p0, p1, agg_a + q * 16);
                FMA2(acc0, p0, app[2 * q]);
                FMA2(acc1, p1, app[2 * q + 1]);
            }
            ADD2(acc0, acc1);
            sh_out[lane][ln] = lrelu(HSUM2(acc0));
        }
        __syncwarp();
    }

    __syncthreads();
    for (int e = threadIdx.x; e < DD * 32; e += 128) {
        int c = e >> 5, ln = e & 31;
        out[((size_t)b * DD + c) * NN + n0 + ln] = sh_out[c][ln];
    }
}

// ---------------------------------------------------------------------------
extern "C" void kernel_launch(void* const* d_in, const int* in_sizes, int n_in,
                              void* d_out, int out_size) {
    const float* xyz     = (const float*)d_in[0];
    const float* feature = (const float*)d_in[1];
    const int*   nidx    = (const int*)  d_in[2];
    const float* w1   = (const float*)d_in[3];
    const float* b1   = (const float*)d_in[4];
    const float* g1   = (const float*)d_in[5];
    const float* be1  = (const float*)d_in[6];
    const float* fc1w = (const float*)d_in[7];
    const float* fc1b = (const float*)d_in[8];
    const float* ap1w = (const float*)d_in[9];
    const float* ap1b = (const float*)d_in[10];
    const float* ap1g = (const float*)d_in[11];
    const float* ap1be= (const float*)d_in[12];
    const float* w2   = (const float*)d_in[13];
    const float* b2   = (const float*)d_in[14];
    const float* g2   = (const float*)d_in[15];
    const float* be2  = (const float*)d_in[16];
    const float* fc2w = (const float*)d_in[17];
    const float* fc2b = (const float*)d_in[18];
    const float* ap2w = (const float*)d_in[19];
    const float* ap2b = (const float*)d_in[20];
    const float* ap2g = (const float*)d_in[21];
    const float* ap2be= (const float*)d_in[22];
    float* out = (float*)d_out;

    transpose_feat_kernel<<<dim3(NN / 64, BB), 256>>>(feature);
    stage1_kernel<<<BB * NN / 32, 128>>>(xyz, nidx, w1, b1, g1, be1,
                                         fc1w, fc1b, ap1w, ap1b, ap1g, ap1be);
    stage2_kernel<<<BB * NN / 32, 128>>>(xyz, nidx, w1, b1, g1, be1,
                                         w2, b2, g2, be2, fc2w, fc2b,
                                         ap2w, ap2b, ap2g, ap2be, out);
}

// round 5
// speedup vs baseline: 1.1486x; 1.0513x over previous
#include <cuda_runtime.h>
#include <math.h>

#define BB 4
#define NN 40960
#define KK 16
#define HH 16
#define DD 32
#define BN_EPS 1e-5f

typedef unsigned long long u64t;

// scratch (device globals: no allocation allowed)
__device__ float g_feat_t[BB * NN * HH];   // feature transposed to [b, n, 16]
__device__ float g_agg1[BB * NN * HH];     // f_agg1 [b, n, 16]

__device__ __forceinline__ float lrelu(float y) { return fmaxf(y, 0.2f * y); }

// ---- packed f32x2 helpers (sm_100+) ----
__device__ __forceinline__ void FMA2(u64t& d, u64t a, u64t b) {
    asm("fma.rn.f32x2 %0, %1, %2, %0;" : "+l"(d) : "l"(a), "l"(b));
}
__device__ __forceinline__ void ADD2(u64t& d, u64t a) {
    asm("add.rn.f32x2 %0, %0, %1;" : "+l"(d) : "l"(a));
}
__device__ __forceinline__ u64t PACK2(float lo, float hi) {
    u64t r; asm("mov.b64 %0, {%1, %2};" : "=l"(r) : "f"(lo), "f"(hi)); return r;
}
__device__ __forceinline__ float HSUM2(u64t v) {
    float lo, hi; asm("mov.b64 {%0, %1}, %2;" : "=f"(lo), "=f"(hi) : "l"(v));
    return lo + hi;
}
__device__ __forceinline__ void LDS2x64(u64t& a, u64t& b, unsigned addr) {
    asm volatile("ld.shared.v2.b64 {%0, %1}, [%2];" : "=l"(a), "=l"(b) : "r"(addr));
}
__device__ __forceinline__ u64t LDS64(unsigned addr) {
    u64t a; asm volatile("ld.shared.b64 %0, [%1];" : "=l"(a) : "r"(addr)); return a;
}

// ---- cp.async helpers ----
__device__ __forceinline__ void cp16(unsigned dst, const float* src) {
    asm volatile("cp.async.cg.shared.global [%0], [%1], 16;" :: "r"(dst), "l"(src));
}
__device__ __forceinline__ void cp4(unsigned dst, const float* src) {
    asm volatile("cp.async.ca.shared.global [%0], [%1], 4;" :: "r"(dst), "l"(src));
}
__device__ __forceinline__ void cp_commit() {
    asm volatile("cp.async.commit_group;");
}
template <int N> __device__ __forceinline__ void cp_wait() {
    asm volatile("cp.async.wait_group %0;" :: "n"(N));
}

// ---------------------------------------------------------------------------
// Transpose feature [B,16,N,1] -> [B*N,16]
// ---------------------------------------------------------------------------
__global__ void transpose_feat_kernel(const float* __restrict__ feature) {
    __shared__ float tile[HH][64 + 1];
    int b = blockIdx.y;
    int n0 = blockIdx.x * 64;
    int t = threadIdx.x;  // 256 threads
    int i = t & 63, cq = t >> 6;
    #pragma unroll
    for (int cc = cq; cc < HH; cc += 4)
        tile[cc][i] = feature[(b * HH + cc) * NN + n0 + i];
    __syncthreads();
    int c = t & 15, iq = t >> 4;
    #pragma unroll
    for (int ii = iq; ii < 64; ii += 16)
        g_feat_t[(b * NN + n0 + ii) * HH + c] = tile[c][ii];
}

// ---------------------------------------------------------------------------
// Stage 1: geometry + conv1(+BN,LReLU) + gather(feat) + att_pool_1 -> g_agg1
// cp.async depth-4 prefetch of all scattered gathers (feat rows + nbr xyz).
// ---------------------------------------------------------------------------
__global__ void __launch_bounds__(128) stage1_kernel(
    const float* __restrict__ xyz, const int* __restrict__ nidx,
    const float* __restrict__ w1, const float* __restrict__ b1,
    const float* __restrict__ g1, const float* __restrict__ be1,
    const float* __restrict__ fc1w, const float* __restrict__ fc1b,
    const float* __restrict__ ap1w, const float* __restrict__ ap1b,
    const float* __restrict__ ap1g, const float* __restrict__ ap1be)
{
    __shared__ __align__(16) float sh_feat[4][4][KK][HH];  // [warp][buf][j][c]
    __shared__ __align__(16) float sh_nxyz[4][4][KK][4];   // [warp][buf][j][xyz-]
    __shared__ __align__(16) float sh_fxyz[4][KK][12];
    __shared__ __align__(16) float sh_conv[4][KK][HH];
    __shared__ __align__(16) float sh_agg[4][DD];
    __shared__ __align__(16) int   sh_idx[4][8][KK];
    __shared__ float sh_cxyz[4][8][3];

    const int warp = threadIdx.x >> 5;
    const int lane = threadIdx.x & 31;
    const int cm16 = lane & 15;
    const float inv_bn = rsqrtf(1.0f + BN_EPS);

    // packed weights (BN folded)
    u64t w1p[5]; float b1f;
    {
        float s = g1[cm16] * inv_bn;
        #pragma unroll
        for (int i = 0; i < 5; i++)
            w1p[i] = PACK2(w1[cm16 * 10 + 2 * i] * s, w1[cm16 * 10 + 2 * i + 1] * s);
        b1f = b1[cm16] * s + be1[cm16];
    }
    u64t fcp[16]; float fcb = fc1b[lane];
    #pragma unroll
    for (int i = 0; i < 16; i++)
        fcp[i] = PACK2(fc1w[lane * DD + 2 * i], fc1w[lane * DD + 2 * i + 1]);
    u64t app[16]; float apb;
    {
        float s = ap1g[cm16] * inv_bn;
        #pragma unroll
        for (int i = 0; i < 16; i++)
            app[i] = PACK2(ap1w[cm16 * DD + 2 * i] * s, ap1w[cm16 * DD + 2 * i + 1] * s);
        apb = ap1b[cm16] * s + ap1be[cm16];
    }

    const int b  = blockIdx.x / (NN / 32);
    const int n0 = (blockIdx.x % (NN / 32)) * 32;
    const int pbase = b * NN + n0 + warp * 8;

    const unsigned feat_a = (unsigned)__cvta_generic_to_shared(&sh_feat[warp][0][0][0]);
    const unsigned nxyz_a = (unsigned)__cvta_generic_to_shared(&sh_nxyz[warp][0][0][0]);
    const unsigned fxyz_a = (unsigned)__cvta_generic_to_shared(&sh_fxyz[warp][0][0]);
    const unsigned conv_a = (unsigned)__cvta_generic_to_shared(&sh_conv[warp][0][0]);
    const unsigned agg_a  = (unsigned)__cvta_generic_to_shared(&sh_agg[warp][0]);

    // hoisted coalesced loads: all 128 indices + 24 center coords
    {
        int4 iv = *(const int4*)(nidx + (size_t)pbase * KK + lane * 4);
        *(int4*)&sh_idx[warp][lane >> 2][(lane & 3) * 4] = iv;
    }
    if (lane < 24) sh_cxyz[warp][lane / 3][lane % 3] = xyz[pbase * 3 + lane];
    __syncwarp();

    const int j2 = lane >> 1, h2 = lane & 1;

    // ---- prologue: issue prefetch groups 0..3 ----
    #pragma unroll
    for (int s = 0; s < 4; s++) {
        int idx = sh_idx[warp][s][j2];
        const float* src = g_feat_t + (size_t)(b * NN + idx) * HH + h2 * 8;
        unsigned d = feat_a + s * 1024 + j2 * 64 + h2 * 32;
        cp16(d, src); cp16(d + 16, src + 4);
        if (lane < KK) {
            int ix = sh_idx[warp][s][lane];
            const float* xs = xyz + (size_t)(b * NN + ix) * 3;
            unsigned dn = nxyz_a + s * 256 + lane * 16;
            cp4(dn, xs); cp4(dn + 4, xs + 1); cp4(dn + 8, xs + 2);
        }
        cp_commit();
    }

    #pragma unroll
    for (int t = 0; t < 8; t++) {
        const int pn = pbase + t;
        const int buf = t & 3;
        if (t < 5) cp_wait<3>(); else if (t == 5) cp_wait<2>();
        else if (t == 6) cp_wait<1>(); else cp_wait<0>();
        __syncwarp();

        // -------- geometry (lane<16) --------
        if (lane < KK) {
            const float* np_ = &sh_nxyz[warp][buf][lane][0];
            float nx = np_[0], ny = np_[1], nz = np_[2];
            float cx = sh_cxyz[warp][t][0], cy = sh_cxyz[warp][t][1], cz = sh_cxyz[warp][t][2];
            float rx = cx - nx, ry = cy - ny, rz = cz - nz;
            float dis = sqrtf(rx * rx + ry * ry + rz * rz);
            float4* row = (float4*)&sh_fxyz[warp][lane][0];
            row[0] = make_float4(dis, rx, ry, rz);
            row[1] = make_float4(cx, cy, cz, nx);
            ((float2*)&sh_fxyz[warp][lane][8])[0] = make_float2(ny, nz);
        }
        __syncwarp();

        // -------- conv1 (10->16) + BN + LReLU -> sh_conv --------
        {
            int jb = (lane >> 4) * 8;
            #pragma unroll
            for (int jj = 0; jj < 8; jj++) {
                int j = jb + jj;
                unsigned a = fxyz_a + j * 48;
                u64t x0, x1, x2, x3, x4;
                LDS2x64(x0, x1, a);
                LDS2x64(x2, x3, a + 16);
                x4 = LDS64(a + 32);
                u64t acc0 = PACK2(b1f, 0.f), acc1 = PACK2(0.f, 0.f);
                FMA2(acc0, x0, w1p[0]); FMA2(acc1, x1, w1p[1]);
                FMA2(acc0, x2, w1p[2]); FMA2(acc1, x3, w1p[3]);
                FMA2(acc0, x4, w1p[4]);
                ADD2(acc0, acc1);
                sh_conv[warp][j][cm16] = lrelu(HSUM2(acc0));
            }
        }
        __syncwarp();

        // -------- fc1 scores + softmax over k + weighted sum --------
        const unsigned fbuf_a = feat_a + buf * 1024;
        float sc[KK];
        #pragma unroll
        for (int j = 0; j < KK; j++) {
            unsigned fa = fbuf_a + j * 64;
            unsigned ca = conv_a + j * 64;
            u64t p0, p1, p2, p3;
            u64t acc0 = PACK2(fcb, 0.f), acc1 = PACK2(0.f, 0.f);
            LDS2x64(p0, p1, fa);      FMA2(acc0, p0, fcp[0]);  FMA2(acc1, p1, fcp[1]);
            LDS2x64(p2, p3, fa + 16); FMA2(acc0, p2, fcp[2]);  FMA2(acc1, p3, fcp[3]);
            LDS2x64(p0, p1, ca);      FMA2(acc0, p0, fcp[8]);  FMA2(acc1, p1, fcp[9]);
            LDS2x64(p2, p3, ca + 16); FMA2(acc0, p2, fcp[10]); FMA2(acc1, p3, fcp[11]);
            LDS2x64(p0, p1, fa + 32); FMA2(acc0, p0, fcp[4]);  FMA2(acc1, p1, fcp[5]);
            LDS2x64(p2, p3, fa + 48); FMA2(acc0, p2, fcp[6]);  FMA2(acc1, p3, fcp[7]);
            LDS2x64(p0, p1, ca + 32); FMA2(acc0, p0, fcp[12]); FMA2(acc1, p1, fcp[13]);
            LDS2x64(p2, p3, ca + 48); FMA2(acc0, p2, fcp[14]); FMA2(acc1, p3, fcp[15]);
            ADD2(acc0, acc1);
            sc[j] = HSUM2(acc0);
        }
        float ssum = 0.0f;
        #pragma unroll
        for (int j = 0; j < KK; j++) { sc[j] = __expf(sc[j]); ssum += sc[j]; }
        float inv = 1.0f / ssum;
        const float* wsp = (lane < HH) ? &sh_feat[warp][buf][0][lane]
                                       : &sh_conv[warp][0][lane - HH];
        float agg = 0.0f;
        #pragma unroll
        for (int j = 0; j < KK; j++)
            agg += wsp[j * HH] * (sc[j] * inv);
        sh_agg[warp][lane] = agg;
        __syncwarp();

        // -------- issue prefetch for t+4 (buffer buf now free) --------
        if (t + 4 < 8) {
            int s = t + 4;
            int idx = sh_idx[warp][s][j2];
            const float* src = g_feat_t + (size_t)(b * NN + idx) * HH + h2 * 8;
            unsigned d = feat_a + (s & 3) * 1024 + j2 * 64 + h2 * 32;
            cp16(d, src); cp16(d + 16, src + 4);
            if (lane < KK) {
                int ix = sh_idx[warp][s][lane];
                const float* xs = xyz + (size_t)(b * NN + ix) * 3;
                unsigned dn = nxyz_a + (s & 3) * 256 + lane * 16;
                cp4(dn, xs); cp4(dn + 4, xs + 1); cp4(dn + 8, xs + 2);
            }
            cp_commit();
        }

        // -------- mlp (32->16) + BN + LReLU, write f_agg1 --------
        if (lane < HH) {
            u64t acc0 = PACK2(apb, 0.f), acc1 = PACK2(0.f, 0.f);
            #pragma unroll
            for (int q = 0; q < 8; q++) {
                u64t p0, p1;
                LDS2x64(p0, p1, agg_a + q * 16);
                FMA2(acc0, p0, app[2 * q]);
                FMA2(acc1, p1, app[2 * q + 1]);
            }
            ADD2(acc0, acc1);
            g_agg1[(size_t)pn * HH + lane] = lrelu(HSUM2(acc0));
        }
        __syncwarp();
    }
}

// ---------------------------------------------------------------------------
// Stage 2: recompute f_xyz1, conv2, gather(f_agg1), att_pool_2 -> output
// ---------------------------------------------------------------------------
__global__ void __launch_bounds__(128) stage2_kernel(
    const float* __restrict__ xyz, const int* __restrict__ nidx,
    const float* __restrict__ w1, const float* __restrict__ b1,
    const float* __restrict__ g1, const float* __restrict__ be1,
    const float* __restrict__ w2, const float* __restrict__ b2,
    const float* __restrict__ g2, const float* __restrict__ be2,
    const float* __restrict__ fc2w, const float* __restrict__ fc2b,
    const float* __restrict__ ap2w, const float* __restrict__ ap2b,
    const float* __restrict__ ap2g, const float* __restrict__ ap2be,
    float* __restrict__ out)
{
    __shared__ __align__(16) float sh_feat[4][4][KK][HH];  // gathered g_agg1
    __shared__ __align__(16) float sh_nxyz[4][4][KK][4];
    __shared__ __align__(16) float sh_fxyz[4][KK][12];
    __shared__ __align__(16) float sh_fx1[4][KK][HH];
    __shared__ __align__(16) float sh_conv[4][KK][HH];
    __shared__ __align__(16) float sh_agg[4][DD];
    __shared__ __align__(16) int   sh_idx[4][8][KK];
    __shared__ float sh_cxyz[4][8][3];
    __shared__ float sh_out[DD][33];

    const int warp = threadIdx.x >> 5;
    const int lane = threadIdx.x & 31;
    const int cm16 = lane & 15;
    const float inv_bn = rsqrtf(1.0f + BN_EPS);

    u64t w1p[5]; float b1f;
    {
        float s = g1[cm16] * inv_bn;
        #pragma unroll
        for (int i = 0; i < 5; i++)
            w1p[i] = PACK2(w1[cm16 * 10 + 2 * i] * s, w1[cm16 * 10 + 2 * i + 1] * s);
        b1f = b1[cm16] * s + be1[cm16];
    }
    u64t w2p[8]; float b2f;
    {
        float s = g2[cm16] * inv_bn;
        #pragma unroll
        for (int i = 0; i < 8; i++)
            w2p[i] = PACK2(w2[cm16 * HH + 2 * i] * s, w2[cm16 * HH + 2 * i + 1] * s);
        b2f = b2[cm16] * s + be2[cm16];
    }
    u64t fcp[16]; float fcb = fc2b[lane];
    #pragma unroll
    for (int i = 0; i < 16; i++)
        fcp[i] = PACK2(fc2w[lane * DD + 2 * i], fc2w[lane * DD + 2 * i + 1]);
    u64t app[16]; float apb;
    {
        float s = ap2g[lane] * inv_bn;
        #pragma unroll
        for (int i = 0; i < 16; i++)
            app[i] = PACK2(ap2w[lane * DD + 2 * i] * s, ap2w[lane * DD + 2 * i + 1] * s);
        apb = ap2b[lane] * s + ap2be[lane];
    }

    const int b  = blockIdx.x / (NN / 32);
    const int n0 = (blockIdx.x % (NN / 32)) * 32;
    const int pbase = b * NN + n0 + warp * 8;

    const unsigned feat_a = (unsigned)__cvta_generic_to_shared(&sh_feat[warp][0][0][0]);
    const unsigned nxyz_a = (unsigned)__cvta_generic_to_shared(&sh_nxyz[warp][0][0][0]);
    const unsigned fxyz_a = (unsigned)__cvta_generic_to_shared(&sh_fxyz[warp][0][0]);
    const unsigned fx1_a  = (unsigned)__cvta_generic_to_shared(&sh_fx1[warp][0][0]);
    const unsigned conv_a = (unsigned)__cvta_generic_to_shared(&sh_conv[warp][0][0]);
    const unsigned agg_a  = (unsigned)__cvta_generic_to_shared(&sh_agg[warp][0]);

    {
        int4 iv = *(const int4*)(nidx + (size_t)pbase * KK + lane * 4);
        *(int4*)&sh_idx[warp][lane >> 2][(lane & 3) * 4] = iv;
    }
    if (lane < 24) sh_cxyz[warp][lane / 3][lane % 3] = xyz[pbase * 3 + lane];
    __syncwarp();

    const int j2 = lane >> 1, h2 = lane & 1;

    #pragma unroll
    for (int s = 0; s < 4; s++) {
        int idx = sh_idx[warp][s][j2];
        const float* src = g_agg1 + (size_t)(b * NN + idx) * HH + h2 * 8;
        unsigned d = feat_a + s * 1024 + j2 * 64 + h2 * 32;
        cp16(d, src); cp16(d + 16, src + 4);
        if (lane < KK) {
            int ix = sh_idx[warp][s][lane];
            const float* xs = xyz + (size_t)(b * NN + ix) * 3;
            unsigned dn = nxyz_a + s * 256 + lane * 16;
            cp4(dn, xs); cp4(dn + 4, xs + 1); cp4(dn + 8, xs + 2);
        }
        cp_commit();
    }

    #pragma unroll
    for (int t = 0; t < 8; t++) {
        const int ln = warp * 8 + t;   // local point in [0,32)
        const int buf = t & 3;
        if (t < 5) cp_wait<3>(); else if (t == 5) cp_wait<2>();
        else if (t == 6) cp_wait<1>(); else cp_wait<0>();
        __syncwarp();

        // geometry
        if (lane < KK) {
            const float* np_ = &sh_nxyz[warp][buf][lane][0];
            float nx = np_[0], ny = np_[1], nz = np_[2];
            float cx = sh_cxyz[warp][t][0], cy = sh_cxyz[warp][t][1], cz = sh_cxyz[warp][t][2];
            float rx = cx - nx, ry = cy - ny, rz = cz - nz;
            float dis = sqrtf(rx * rx + ry * ry + rz * rz);
            float4* row = (float4*)&sh_fxyz[warp][lane][0];
            row[0] = make_float4(dis, rx, ry, rz);
            row[1] = make_float4(cx, cy, cz, nx);
            ((float2*)&sh_fxyz[warp][lane][8])[0] = make_float2(ny, nz);
        }
        __syncwarp();

        // conv1 recompute (10->16) -> sh_fx1
        {
            int jb = (lane >> 4) * 8;
            #pragma unroll
            for (int jj = 0; jj < 8; jj++) {
                int j = jb + jj;
                unsigned a = fxyz_a + j * 48;
                u64t x0, x1, x2, x3, x4;
                LDS2x64(x0, x1, a);
                LDS2x64(x2, x3, a + 16);
                x4 = LDS64(a + 32);
                u64t acc0 = PACK2(b1f, 0.f), acc1 = PACK2(0.f, 0.f);
                FMA2(acc0, x0, w1p[0]); FMA2(acc1, x1, w1p[1]);
                FMA2(acc0, x2, w1p[2]); FMA2(acc1, x3, w1p[3]);
                FMA2(acc0, x4, w1p[4]);
                ADD2(acc0, acc1);
                sh_fx1[warp][j][cm16] = lrelu(HSUM2(acc0));
            }
        }
        __syncwarp();

        // conv2 (16->16) + BN + LReLU -> sh_conv
        {
            int jb = (lane >> 4) * 8;
            #pragma unroll
            for (int jj = 0; jj < 8; jj++) {
                int j = jb + jj;
                unsigned a = fx1_a + j * 64;
                u64t p0, p1, p2, p3;
                u64t acc0 = PACK2(b2f, 0.f), acc1 = PACK2(0.f, 0.f);
                LDS2x64(p0, p1, a);      FMA2(acc0, p0, w2p[0]); FMA2(acc1, p1, w2p[1]);
                LDS2x64(p2, p3, a + 16); FMA2(acc0, p2, w2p[2]); FMA2(acc1, p3, w2p[3]);
                LDS2x64(p0, p1, a + 32); FMA2(acc0, p0, w2p[4]); FMA2(acc1, p1, w2p[5]);
                LDS2x64(p2, p3, a + 48); FMA2(acc0, p2, w2p[6]); FMA2(acc1, p3, w2p[7]);
                ADD2(acc0, acc1);
                sh_conv[warp][j][cm16] = lrelu(HSUM2(acc0));
            }
        }
        __syncwarp();

        // fc2 + softmax + weighted sum
        const unsigned fbuf_a = feat_a + buf * 1024;
        float sc[KK];
        #pragma unroll
        for (int j = 0; j < KK; j++) {
            unsigned fa = fbuf_a + j * 64;
            unsigned ca = conv_a + j * 64;
            u64t p0, p1, p2, p3;
            u64t acc0 = PACK2(fcb, 0.f), acc1 = PACK2(0.f, 0.f);
            LDS2x64(p0, p1, fa);      FMA2(acc0, p0, fcp[0]);  FMA2(acc1, p1, fcp[1]);
            LDS2x64(p2, p3, fa + 16); FMA2(acc0, p2, fcp[2]);  FMA2(acc1, p3, fcp[3]);
            LDS2x64(p0, p1, ca);      FMA2(acc0, p0, fcp[8]);  FMA2(acc1, p1, fcp[9]);
            LDS2x64(p2, p3, ca + 16); FMA2(acc0, p2, fcp[10]); FMA2(acc1, p3, fcp[11]);
            LDS2x64(p0, p1, fa + 32); FMA2(acc0, p0, fcp[4]);  FMA2(acc1, p1, fcp[5]);
            LDS2x64(p2, p3, fa + 48); FMA2(acc0, p2, fcp[6]);  FMA2(acc1, p3, fcp[7]);
            LDS2x64(p0, p1, ca + 32); FMA2(acc0, p0, fcp[12]); FMA2(acc1, p1, fcp[13]);
            LDS2x64(p2, p3, ca + 48); FMA2(acc0, p2, fcp[14]); FMA2(acc1, p3, fcp[15]);
            ADD2(acc0, acc1);
            sc[j] = HSUM2(acc0);
        }
        float ssum = 0.0f;
        #pragma unroll
        for (int j = 0; j < KK; j++) { sc[j] = __expf(sc[j]); ssum += sc[j]; }
        float inv = 1.0f / ssum;
        const float* wsp = (lane < HH) ? &sh_feat[warp][buf][0][lane]
                                       : &sh_conv[warp][0][lane - HH];
        float agg = 0.0f;
        #pragma unroll
        for (int j = 0; j < KK; j++)
            agg += wsp[j * HH] * (sc[j] * inv);
        sh_agg[warp][lane] = agg;
        __syncwarp();

        // issue prefetch for t+4 (buffer free now)
        if (t + 4 < 8) {
            int s = t + 4;
            int idx = sh_idx[warp][s][j2];
            const float* src = g_agg1 + (size_t)(b * NN + idx) * HH + h2 * 8;
            unsigned d = feat_a + (s & 3) * 1024 + j2 * 64 + h2 * 32;
            cp16(d, src); cp16(d + 16, src + 4);
            if (lane < KK) {
                int ix = sh_idx[warp][s][lane];
                const float* xs = xyz + (size_t)(b * NN + ix) * 3;
                unsigned dn = nxyz_a + (s & 3) * 256 + lane * 16;
                cp4(dn, xs); cp4(dn + 4, xs + 1); cp4(dn + 8, xs + 2);
            }
            cp_commit();
        }

        // mlp2 (32->32) + BN + LReLU -> staged output
        {
            u64t acc0 = PACK2(apb, 0.f), acc1 = PACK2(0.f, 0.f);
            #pragma unroll
            for (int q = 0; q < 8; q++) {
                u64t p0, p1;
                LDS2x64(p0, p1, agg_a + q * 16);
                FMA2(acc0, p0, app[2 * q]);
                FMA2(acc1, p1, app[2 * q + 1]);
            }
            ADD2(acc0, acc1);
            sh_out[lane][ln] = lrelu(HSUM2(acc0));
        }
        __syncwarp();
    }

    __syncthreads();
    for (int e = threadIdx.x; e < DD * 32; e += 128) {
        int c = e >> 5, ln = e & 31;
        out[((size_t)b * DD + c) * NN + n0 + ln] = sh_out[c][ln];
    }
}

// ---------------------------------------------------------------------------
extern "C" void kernel_launch(void* const* d_in, const int* in_sizes, int n_in,
                              void* d_out, int out_size) {
    const float* xyz     = (const float*)d_in[0];
    const float* feature = (const float*)d_in[1];
    const int*   nidx    = (const int*)  d_in[2];
    const float* w1   = (const float*)d_in[3];
    const float* b1   = (const float*)d_in[4];
    const float* g1   = (const float*)d_in[5];
    const float* be1  = (const float*)d_in[6];
    const float* fc1w = (const float*)d_in[7];
    const float* fc1b = (const float*)d_in[8];
    const float* ap1w = (const float*)d_in[9];
    const float* ap1b = (const float*)d_in[10];
    const float* ap1g = (const float*)d_in[11];
    const float* ap1be= (const float*)d_in[12];
    const float* w2   = (const float*)d_in[13];
    const float* b2   = (const float*)d_in[14];
    const float* g2   = (const float*)d_in[15];
    const float* be2  = (const float*)d_in[16];
    const float* fc2w = (const float*)d_in[17];
    const float* fc2b = (const float*)d_in[18];
    const float* ap2w = (const float*)d_in[19];
    const float* ap2b = (const float*)d_in[20];
    const float* ap2g = (const float*)d_in[21];
    const float* ap2be= (const float*)d_in[22];
    float* out = (float*)d_out;

    transpose_feat_kernel<<<dim3(NN / 64, BB), 256>>>(feature);
    stage1_kernel<<<BB * NN / 32, 128>>>(xyz, nidx, w1, b1, g1, be1,
                                         fc1w, fc1b, ap1w, ap1b, ap1g, ap1be);
    stage2_kernel<<<BB * NN / 32, 128>>>(xyz, nidx, w1, b1, g1, be1,
                                         w2, b2, g2, be2, fc2w, fc2b,
                                         ap2w, ap2b, ap2g, ap2be, out);
}